// round 14
// baseline (speedup 1.0000x reference)
#include <cuda_runtime.h>
#include <cstdint>

#define S_TOKENS 16384
#define D_MODEL  4096
#define N_EXP    64
#define TM       128
#define NCTA     (S_TOKENS / TM)   // 128
#define NITER    (D_MODEL / 32)    // 128 chunks of K=32
#define NSTAGE   4
#define X_ROW_B  160
#define W_ROW_B  160
#define X_BYTES  (TM * X_ROW_B)      // 20480
#define W_BYTES  (N_EXP * W_ROW_B)   // 10240
#define STAGE_B  (X_BYTES + W_BYTES) // 30720
#define MB_OFF   (NSTAGE * STAGE_B)  // 122880; full at +st*16, empty at +st*16+8
#define SMEM_B   (MB_OFF + NSTAGE * 16)
#define L_STR    65
#define DELTA    1e-3f
#define NTHR     288               // 8 consumer warps + 1 producer warp

// W pre-split into (bf16x2 hi-pair, bf16x2 lo-pair), chunk-major:
// [chunk][expert][16 uint2] -> 128B per expert row, 8KB blob per chunk
__device__ __align__(16) uint2 w_split[NITER * N_EXP * 16];
__device__ float        part_imp[NCTA][N_EXP];
__device__ int          part_cnt[NCTA][N_EXP];
__device__ unsigned int g_ctr = 0;

__device__ __forceinline__ void split2(float2 v, uint32_t& h, uint32_t& l) {
    asm("cvt.rn.bf16x2.f32 %0, %1, %2;" : "=r"(h) : "f"(v.y), "f"(v.x));
    float h0 = __uint_as_float(h << 16);
    float h1 = __uint_as_float(h & 0xffff0000u);
    float l0 = v.x - h0, l1 = v.y - h1;
    asm("cvt.rn.bf16x2.f32 %0, %1, %2;" : "=r"(l) : "f"(l1), "f"(l0));
}

__device__ __forceinline__ void mma_bf16(float* c,
                                         uint32_t a0, uint32_t a1,
                                         uint32_t a2, uint32_t a3,
                                         uint32_t b0, uint32_t b1) {
    asm volatile(
        "mma.sync.aligned.m16n8k16.row.col.f32.bf16.bf16.f32 "
        "{%0,%1,%2,%3}, {%4,%5,%6,%7}, {%8,%9}, {%0,%1,%2,%3};"
        : "+f"(c[0]), "+f"(c[1]), "+f"(c[2]), "+f"(c[3])
        : "r"(a0), "r"(a1), "r"(a2), "r"(a3), "r"(b0), "r"(b1));
}

#define MBARRIER_INIT(mbar, count) \
    asm volatile("mbarrier.init.shared.b64 [%0], %1;" \
        :: "r"((uint32_t)(mbar)), "r"((uint32_t)(count)) : "memory")
#define MBARRIER_ARRIVE(mbar) \
    asm volatile("mbarrier.arrive.shared.b64 _, [%0];" \
        :: "r"((uint32_t)(mbar)) : "memory")
#define CPASYNC_MBAR_ARRIVE_NOINC(mbar) \
    asm volatile("cp.async.mbarrier.arrive.noinc.shared.b64 [%0];" \
        :: "r"((uint32_t)(mbar)) : "memory")
#define MBARRIER_WAIT_PARITY(mbar_addr, phase_parity) do { \
    uint32_t _mbar = (uint32_t)(mbar_addr); \
    uint32_t _par = (uint32_t)(phase_parity); \
    uint32_t _done; \
    asm volatile("{\n\t.reg .pred p;\n\t" \
        "mbarrier.try_wait.parity.acquire.cta.shared::cta.b64 p, [%1], %2;\n\t" \
        "selp.b32 %0, 1, 0, p;\n\t}" \
        : "=r"(_done) : "r"(_mbar), "r"(_par) : "memory"); \
    if (!_done) { \
        asm volatile("{\n\t.reg .pred P1;\n\t" \
            "WAIT_LOOP_%=:\n\t" \
            "mbarrier.try_wait.parity.acquire.cta.shared::cta.b64 P1, [%0], %1, 0x989680;\n\t" \
            "@P1 bra.uni WAIT_DONE_%=;\n\t" \
            "bra.uni WAIT_LOOP_%=;\n\t" \
            "WAIT_DONE_%=:\n\t}" \
            :: "r"(_mbar), "r"(_par) : "memory"); \
    } \
} while(0)

__global__ void prep_kernel(const float* __restrict__ wg) {
    const int e = blockIdx.x;
    const int tid = threadIdx.x;
    const float2* wrow = (const float2*)(wg + (size_t)e * D_MODEL);
#pragma unroll
    for (int i = 0; i < 8; i++) {
        int kp = i * 256 + tid;          // global k-pair 0..2047
        float2 v = wrow[kp];
        uint32_t h, l;
        split2(v, h, l);
        int c = kp >> 4, kl = kp & 15;
        w_split[(size_t)c * (N_EXP * 16) + e * 16 + kl] = make_uint2(h, l);
    }
}

__global__ __launch_bounds__(NTHR, 1)
void gate_kernel(const float* __restrict__ x,
                 const float* __restrict__ wg,
                 float* __restrict__ out)
{
    extern __shared__ char smem[];
    uint32_t sb;
    asm("{ .reg .u64 t; cvta.to.shared.u64 t, %1; cvt.u32.u64 %0, t; }"
        : "=r"(sb) : "l"(smem));

    const int tid     = threadIdx.x;
    const int lane    = tid & 31;
    const int wid     = tid >> 5;          // 0..8
    const int blk     = blockIdx.x;
    const int tokBase = blk * TM;

    if (tid == 0) {
#pragma unroll
        for (int s = 0; s < NSTAGE; s++) {
            MBARRIER_INIT(sb + MB_OFF + s * 16, 32);       // full: producer warp
            MBARRIER_INIT(sb + MB_OFF + s * 16 + 8, 256);  // empty: consumer threads
        }
    }
    __syncthreads();

    if (wid == 8) {
        // ================= producer warp =================
        // per chunk: X 128 rows x 128B (4 rows/thread), W 64 rows x 128B (2 rows/thread)
        const char* xp[4];
        uint32_t    xd[4];
        const char* wp[2];
        uint32_t    wd[2];
#pragma unroll
        for (int rr = 0; rr < 4; rr++) {
            int row = lane * 4 + rr;
            xp[rr] = (const char*)(x + (size_t)(tokBase + row) * D_MODEL);
            xd[rr] = (uint32_t)(row * X_ROW_B);
        }
#pragma unroll
        for (int rr = 0; rr < 2; rr++) {
            int row = lane * 2 + rr;
            wp[rr] = (const char*)w_split + row * 128;
            wd[rr] = (uint32_t)(X_BYTES + row * W_ROW_B);
        }

        for (int c = 0; c < NITER; c++) {
            const int st = c & 3;
            if (c >= NSTAGE)
                MBARRIER_WAIT_PARITY(sb + MB_OFF + st * 16 + 8, ((c >> 2) + 1) & 1);

            const uint32_t bs = sb + (uint32_t)st * STAGE_B;
#pragma unroll
            for (int rr = 0; rr < 4; rr++) {
                const char* src = xp[rr] + (size_t)c * 128;
#pragma unroll
                for (int cc = 0; cc < 8; cc++)
                    asm volatile("cp.async.cg.shared.global [%0], [%1], 16;"
                        :: "r"(bs + xd[rr] + cc * 16), "l"(src + cc * 16) : "memory");
            }
#pragma unroll
            for (int rr = 0; rr < 2; rr++) {
                const char* src = wp[rr] + (size_t)c * 8192;
#pragma unroll
                for (int cc = 0; cc < 8; cc++)
                    asm volatile("cp.async.cg.shared.global [%0], [%1], 16;"
                        :: "r"(bs + wd[rr] + cc * 16), "l"(src + cc * 16) : "memory");
            }
            CPASYNC_MBAR_ARRIVE_NOINC(sb + MB_OFF + st * 16);
        }
    } else {
        // ================= consumer warps (0..7) =================
        const int r   = lane >> 2;   // 0..7
        const int ci  = lane & 3;    // 0..3
        const int m0  = wid * 16;

        float acc0[8][4], acc1[8][4], acc2[8][4];
#pragma unroll
        for (int n = 0; n < 8; n++)
#pragma unroll
            for (int q = 0; q < 4; q++) { acc0[n][q] = 0.f; acc1[n][q] = 0.f; acc2[n][q] = 0.f; }

        const int abase0 = (m0 + r) * 20 + ci;   // float2 units
        const int bbase0 = r * 20 + ci;          // uint2 units

        for (int c = 0; c < NITER; c++) {
            const int st = c & 3;
            MBARRIER_WAIT_PARITY(sb + MB_OFF + st * 16, (c >> 2) & 1);

            const float2* X2 = (const float2*)(smem + st * STAGE_B);
            const uint2*  W2 = (const uint2*)(smem + st * STAGE_B + X_BYTES);

#pragma unroll
            for (int ks = 0; ks < 2; ks++) {
                const int abase = abase0 + ks * 8;
                float2 v00 = X2[abase];
                float2 v10 = X2[abase + 160];
                float2 v01 = X2[abase + 4];
                float2 v11 = X2[abase + 164];
                uint32_t ah0, al0, ah1, al1, ah2, al2, ah3, al3;
                split2(v00, ah0, al0);
                split2(v10, ah1, al1);
                split2(v01, ah2, al2);
                split2(v11, ah3, al3);

                const int bbase = bbase0 + ks * 8;
#pragma unroll
                for (int n = 0; n < 8; n++) {
                    uint2 q0 = W2[bbase + n * 160];
                    uint2 q1 = W2[bbase + n * 160 + 4];
                    mma_bf16(acc0[n], ah0, ah1, ah2, ah3, q0.x, q1.x);  // hh
                    mma_bf16(acc1[n], ah0, ah1, ah2, ah3, q0.y, q1.y);  // hl
                    mma_bf16(acc2[n], al0, al1, al2, al3, q0.x, q1.x);  // lh
                }
            }
            MBARRIER_ARRIVE(sb + MB_OFF + st * 16 + 8);
        }

        // stash logits to smem AFTER the barrier below (acc regs live across)
        __syncthreads();   // (A) all pipeline traffic done

        float* Lp = (float*)smem;   // [128][65] overlays stages
#pragma unroll
        for (int n = 0; n < 8; n++) {
            const int col = n * 8 + 2 * ci;
            Lp[(m0 + r)     * L_STR + col]     = acc0[n][0] + acc1[n][0] + acc2[n][0];
            Lp[(m0 + r)     * L_STR + col + 1] = acc0[n][1] + acc1[n][1] + acc2[n][1];
            Lp[(m0 + r + 8) * L_STR + col]     = acc0[n][2] + acc1[n][2] + acc2[n][2];
            Lp[(m0 + r + 8) * L_STR + col + 1] = acc0[n][3] + acc1[n][3] + acc2[n][3];
        }
    }
    if (wid == 8) __syncthreads();   // (A) producer side of the same barrier

    // ---- epilogue smem layout (overlays stages) ----
    float* smf   = (float*)smem;
    float* Lp    = smf;                         // [128][65]
    float* tmax  = smf + TM * L_STR;
    float* tm2   = tmax + TM;
    float* trcp  = tm2 + TM;
    int*   hist  = (int*)(trcp + TM);
    int*   i1s   = (int*)(hist + N_EXP);
    int*   wl    = (int*)(i1s + TM);
    int*   nflag = (int*)(wl + TM);
    float* simp  = (float*)(nflag + 4);
    int*   slast = (int*)(simp + N_EXP);

    if (tid < N_EXP) { hist[tid] = 0; simp[tid] = 0.0f; }
    if (tid == 0) nflag[0] = 0;
    __syncthreads();                 // (B) logits + zeroed scratch visible

    // phase A: per-token top-3 + softmax stats + provisional outputs
    if (tid < TM) {
        const int t = tid;
        float m1 = -1e30f, m2v = -1e30f, m3v = -1e30f;
        int i1 = 0, i2 = 0;
#pragma unroll
        for (int e = 0; e < N_EXP; e++) {
            float v = Lp[t * L_STR + e];
            if (v > m1)       { m3v = m2v; m2v = m1; i2 = i1; m1 = v; i1 = e; }
            else if (v > m2v) { m3v = m2v; m2v = v;  i2 = e; }
            else if (v > m3v) { m3v = v; }
        }
        float s = 0.0f;
#pragma unroll
        for (int e = 0; e < N_EXP; e++) s += __expf(Lp[t * L_STR + e] - m1);
        float rcp = 1.0f / s;

        const int gt = tokBase + t;
        out[(size_t)gt * 2 + 0] = (float)i1;
        out[(size_t)gt * 2 + 1] = (float)i2;
        out[(size_t)2 * S_TOKENS + (size_t)gt * 2 + 0] = rcp;
        out[(size_t)2 * S_TOKENS + (size_t)gt * 2 + 1] = __expf(m2v - m1) * rcp;

        tmax[t] = m1;
        tm2[t]  = m2v;
        trcp[t] = rcp;
        i1s[t]  = i1;
        atomicAdd(&hist[i1], 1);

        if ((m1 - m2v) < DELTA || (m2v - m3v) < DELTA) {
            int idx = atomicAdd(nflag, 1);
            wl[idx] = t;
        }
    }
    __syncthreads();

    // near-tie repair: exact fp32 recompute (warp per token)
    {
        const int nf = nflag[0];
        for (int wi = wid; wi < nf; wi += 9) {
            const int t = wl[wi];
            const float thresh = tm2[t] - DELTA;
            const float4* xr4 = (const float4*)(x + (size_t)(tokBase + t) * D_MODEL);
            float e1 = -1e30f, e2 = -1e30f;
            int j1 = 0, j2 = 0;
            for (int e = 0; e < N_EXP; e++) {
                if (Lp[t * L_STR + e] >= thresh) {
                    const float4* wr4 = (const float4*)(wg + (size_t)e * D_MODEL);
                    float s = 0.0f;
#pragma unroll 4
                    for (int i = lane; i < D_MODEL / 4; i += 32) {
                        float4 xv = xr4[i];
                        float4 wv = wr4[i];
                        s += xv.x * wv.x; s += xv.y * wv.y;
                        s += xv.z * wv.z; s += xv.w * wv.w;
                    }
#pragma unroll
                    for (int o = 16; o > 0; o >>= 1)
                        s += __shfl_xor_sync(0xffffffffu, s, o);
                    if (s > e1)      { e2 = e1; j2 = j1; e1 = s; j1 = e; }
                    else if (s > e2) { e2 = s;  j2 = e; }
                }
            }
            if (lane == 0) {
                const int gt = tokBase + t;
                out[(size_t)gt * 2 + 0] = (float)j1;
                out[(size_t)gt * 2 + 1] = (float)j2;
                out[(size_t)2 * S_TOKENS + (size_t)gt * 2 + 0] =
                    __expf(e1 - tmax[t]) * trcp[t];
                out[(size_t)2 * S_TOKENS + (size_t)gt * 2 + 1] =
                    __expf(e2 - tmax[t]) * trcp[t];
                if (j1 != i1s[t]) {
                    atomicAdd(&hist[i1s[t]], -1);
                    atomicAdd(&hist[j1], 1);
                }
            }
        }
    }
    __syncthreads();

    // phase B: per-CTA importance partials -> global scratch
    if (tid < 256) {
        const int e = tid & 63;
        const int g = tid >> 6;      // 4 groups of 32 tokens
        float p = 0.0f;
#pragma unroll
        for (int rr = 0; rr < 32; rr++) {
            int t = g * 32 + rr;
            p += __expf(Lp[t * L_STR + e] - tmax[t]) * trcp[t];
        }
        atomicAdd(&simp[e], p);
    }
    __syncthreads();
    if (tid < N_EXP) {
        part_imp[blk][tid] = simp[tid];
        part_cnt[blk][tid] = hist[tid];
    }

    // ---- last-CTA finalize ----
    __threadfence();
    __syncthreads();
    if (tid == 0) {
        unsigned int old = atomicAdd(&g_ctr, 1u);
        slast[0] = (old == NCTA - 1) ? 1 : 0;
    }
    __syncthreads();
    if (slast[0]) {
        float v = 0.0f;
        if (tid < N_EXP) {
            float vi = 0.0f;
            int   cc = 0;
            for (int cta = 0; cta < NCTA; cta++) {
                vi += part_imp[cta][tid];
                cc += part_cnt[cta][tid];
            }
            v = vi * (float)cc;
        }
#pragma unroll
        for (int o = 16; o > 0; o >>= 1) v += __shfl_down_sync(0xffffffffu, v, o);
        if (tid == 32) simp[1] = v;
        __syncthreads();
        if (tid == 0) {
            float tot = v + simp[1];
            out[(size_t)4 * S_TOKENS] =
                (float)N_EXP * tot / ((float)S_TOKENS * (float)S_TOKENS);
            g_ctr = 0;
        }
    }
}

extern "C" void kernel_launch(void* const* d_in, const int* in_sizes, int n_in,
                              void* d_out, int out_size)
{
    const float* x  = (const float*)d_in[0];
    const float* wg = (const float*)d_in[1];
    float* out = (float*)d_out;

    static int configured = 0;
    if (!configured) {
        cudaFuncSetAttribute(gate_kernel,
                             cudaFuncAttributeMaxDynamicSharedMemorySize, SMEM_B);
        configured = 1;
    }

    prep_kernel<<<N_EXP, 256>>>(wg);
    gate_kernel<<<NCTA, NTHR, SMEM_B>>>(x, wg, out);
}

// round 16
// speedup vs baseline: 1.4221x; 1.4221x over previous
#include <cuda_runtime.h>
#include <cstdint>

#define S_TOKENS 16384
#define D_MODEL  4096
#define N_EXP    64
#define TM       128
#define NCTA     (S_TOKENS / TM)   // 128
#define NITER    (D_MODEL / 32)    // 128 chunks of K=32
#define NSTAGE   6
#define X_ROW_B  160               // 32 floats data + pad
#define W_ROW_B  160               // 16 uint2 data + pad
#define X_BYTES  (TM * X_ROW_B)    // 20480
#define W_BYTES  (N_EXP * W_ROW_B) // 10240
#define STAGE_B  (X_BYTES + W_BYTES) // 30720
#define SMEM_B   (NSTAGE * STAGE_B)  // 184320
#define L_STR    65
#define DELTA    1e-3f
#define NTHR     256

// W pre-split into (bf16x2 hi-pair, bf16x2 lo-pair), chunk-major:
// [chunk][expert][16 uint2] -> 128B data per expert row
__device__ __align__(16) uint2 w_split[NITER * N_EXP * 16];
__device__ float        part_imp[NCTA][N_EXP];
__device__ int          part_cnt[NCTA][N_EXP];
__device__ unsigned int g_ctr = 0;

__device__ __forceinline__ void split2(float2 v, uint32_t& h, uint32_t& l) {
    asm("cvt.rn.bf16x2.f32 %0, %1, %2;" : "=r"(h) : "f"(v.y), "f"(v.x));
    float h0 = __uint_as_float(h << 16);
    float h1 = __uint_as_float(h & 0xffff0000u);
    float l0 = v.x - h0, l1 = v.y - h1;
    asm("cvt.rn.bf16x2.f32 %0, %1, %2;" : "=r"(l) : "f"(l1), "f"(l0));
}

__device__ __forceinline__ void mma_bf16(float* c,
                                         uint32_t a0, uint32_t a1,
                                         uint32_t a2, uint32_t a3,
                                         uint32_t b0, uint32_t b1) {
    asm volatile(
        "mma.sync.aligned.m16n8k16.row.col.f32.bf16.bf16.f32 "
        "{%0,%1,%2,%3}, {%4,%5,%6,%7}, {%8,%9}, {%0,%1,%2,%3};"
        : "+f"(c[0]), "+f"(c[1]), "+f"(c[2]), "+f"(c[3])
        : "r"(a0), "r"(a1), "r"(a2), "r"(a3), "r"(b0), "r"(b1));
}

__global__ void prep_kernel(const float* __restrict__ wg) {
    const int e = blockIdx.x;
    const int tid = threadIdx.x;
    const float2* wrow = (const float2*)(wg + (size_t)e * D_MODEL);
#pragma unroll
    for (int i = 0; i < 8; i++) {
        int kp = i * 256 + tid;          // global k-pair 0..2047
        float2 v = wrow[kp];
        uint32_t h, l;
        split2(v, h, l);
        int c = kp >> 4, kl = kp & 15;
        w_split[(size_t)c * (N_EXP * 16) + e * 16 + kl] = make_uint2(h, l);
    }
}

__global__ __launch_bounds__(NTHR, 1)
void gate_kernel(const float* __restrict__ x,
                 const float* __restrict__ wg,
                 float* __restrict__ out)
{
    extern __shared__ char smem[];
    uint32_t sb;
    asm("{ .reg .u64 t; cvta.to.shared.u64 t, %1; cvt.u32.u64 %0, t; }"
        : "=r"(sb) : "l"(smem));

    const int tid     = threadIdx.x;
    const int lane    = tid & 31;
    const int wid     = tid >> 5;          // 0..7
    const int blk     = blockIdx.x;
    const int tokBase = blk * TM;

    // ---- cp.async copy mapping (6 x 16B per thread per chunk) ----
    const int trow = tid >> 3;             // 0..31
    const int p16  = (tid & 7) * 16;
    const uint32_t xoff = (uint32_t)(trow * X_ROW_B + p16);
    const uint32_t woff = (uint32_t)(trow * W_ROW_B + p16);
    const char* xsrc = (const char*)x +
                       ((size_t)(tokBase + trow) * D_MODEL) * 4 + p16;
    const char* wsrc = (const char*)w_split + trow * 128 + p16;

#define ISSUE(st, cc) do {                                                   \
    uint32_t dx = sb + (uint32_t)(st) * STAGE_B + xoff;                      \
    const char* sx = xsrc + (size_t)(cc) * 128;                              \
    _Pragma("unroll")                                                        \
    for (int j = 0; j < 4; j++)                                              \
        asm volatile("cp.async.cg.shared.global [%0], [%1], 16;"             \
            :: "r"(dx + j * (32 * X_ROW_B)),                                 \
               "l"(sx + (size_t)j * 32 * (D_MODEL * 4)) : "memory");         \
    uint32_t dw = sb + (uint32_t)(st) * STAGE_B + X_BYTES + woff;            \
    const char* sw = wsrc + (size_t)(cc) * 8192;                             \
    _Pragma("unroll")                                                        \
    for (int j = 0; j < 2; j++)                                              \
        asm volatile("cp.async.cg.shared.global [%0], [%1], 16;"             \
            :: "r"(dw + j * (32 * W_ROW_B)),                                 \
               "l"(sw + j * (32 * 128)) : "memory");                         \
} while (0)

    // prologue: two groups of two chunks each (stages 0..3)
    ISSUE(0, 0); ISSUE(1, 1);
    asm volatile("cp.async.commit_group;" ::: "memory");
    ISSUE(2, 2); ISSUE(3, 3);
    asm volatile("cp.async.commit_group;" ::: "memory");

    // ---- compute mapping: each warp = 16 tokens x 64 experts ----
    const int r  = lane >> 2;   // 0..7
    const int ci = lane & 3;    // 0..3
    const int m0 = wid * 16;

    float acc0[8][4], acc1[8][4], acc2[8][4];
#pragma unroll
    for (int n = 0; n < 8; n++)
#pragma unroll
        for (int q = 0; q < 4; q++) { acc0[n][q] = 0.f; acc1[n][q] = 0.f; acc2[n][q] = 0.f; }

    const int abase00 = (m0 + r) * 20 + ci;   // float2 units
    const int bbase00 = r * 20 + ci;          // uint2 units

    for (int it = 0; it < NITER / 2; it++) {
        // oldest pending pair done -> stages (2it)%6, (2it+1)%6 ready
        asm volatile("cp.async.wait_group 1;" ::: "memory");
        __syncthreads();

        // refill: chunks 2it+4, 2it+5 into stages computed last iteration
        if (2 * it + 4 < NITER) {
            ISSUE((2 * it + 4) % 6, 2 * it + 4);
            ISSUE((2 * it + 5) % 6, 2 * it + 5);
        }
        asm volatile("cp.async.commit_group;" ::: "memory");

        // compute the two ready chunks back-to-back
#pragma unroll
        for (int cc = 0; cc < 2; cc++) {
            const int st = (2 * it + cc) % 6;
            const float2* X2 = (const float2*)(smem + st * STAGE_B);
            const uint2*  W2 = (const uint2*)(smem + st * STAGE_B + X_BYTES);

#pragma unroll
            for (int ks = 0; ks < 2; ks++) {
                const int abase = abase00 + ks * 8;
                float2 v00 = X2[abase];
                float2 v10 = X2[abase + 160];
                float2 v01 = X2[abase + 4];
                float2 v11 = X2[abase + 164];
                uint32_t ah0, al0, ah1, al1, ah2, al2, ah3, al3;
                split2(v00, ah0, al0);
                split2(v10, ah1, al1);
                split2(v01, ah2, al2);
                split2(v11, ah3, al3);

                const int bbase = bbase00 + ks * 8;
#pragma unroll
                for (int n = 0; n < 8; n++) {
                    uint2 q0 = W2[bbase + n * 160];
                    uint2 q1 = W2[bbase + n * 160 + 4];
                    mma_bf16(acc0[n], ah0, ah1, ah2, ah3, q0.x, q1.x);  // hh
                    mma_bf16(acc1[n], ah0, ah1, ah2, ah3, q0.y, q1.y);  // hl
                    mma_bf16(acc2[n], al0, al1, al2, al3, q0.x, q1.x);  // lh
                }
            }
        }
    }
    asm volatile("cp.async.wait_group 0;" ::: "memory");
    __syncthreads();   // gemm smem dead; reuse for epilogue
#undef ISSUE

    // ---- epilogue smem layout (overlays stages) ----
    float* smf   = (float*)smem;
    float* Lp    = smf;                         // [128][65] logits
    float* tmax  = smf + TM * L_STR;
    float* tm2   = tmax + TM;
    float* trcp  = tm2 + TM;
    int*   hist  = (int*)(trcp + TM);
    int*   i1s   = (int*)(hist + N_EXP);
    int*   wl    = (int*)(i1s + TM);
    int*   nflag = (int*)(wl + TM);
    float* simp  = (float*)(nflag + 4);
    int*   slast = (int*)(simp + N_EXP);

    // scatter merged accumulators to L
#pragma unroll
    for (int n = 0; n < 8; n++) {
        const int col = n * 8 + 2 * ci;
        Lp[(m0 + r)     * L_STR + col]     = acc0[n][0] + acc1[n][0] + acc2[n][0];
        Lp[(m0 + r)     * L_STR + col + 1] = acc0[n][1] + acc1[n][1] + acc2[n][1];
        Lp[(m0 + r + 8) * L_STR + col]     = acc0[n][2] + acc1[n][2] + acc2[n][2];
        Lp[(m0 + r + 8) * L_STR + col + 1] = acc0[n][3] + acc1[n][3] + acc2[n][3];
    }
    if (tid < N_EXP) { hist[tid] = 0; simp[tid] = 0.0f; }
    if (tid == 0) nflag[0] = 0;
    __syncthreads();

    // phase A: per-token top-3 + softmax stats + provisional outputs
    if (tid < TM) {
        const int t = tid;
        float m1 = -1e30f, m2v = -1e30f, m3v = -1e30f;
        int i1 = 0, i2 = 0;
#pragma unroll
        for (int e = 0; e < N_EXP; e++) {
            float v = Lp[t * L_STR + e];
            if (v > m1)       { m3v = m2v; m2v = m1; i2 = i1; m1 = v; i1 = e; }
            else if (v > m2v) { m3v = m2v; m2v = v;  i2 = e; }
            else if (v > m3v) { m3v = v; }
        }
        float s = 0.0f;
#pragma unroll
        for (int e = 0; e < N_EXP; e++) s += __expf(Lp[t * L_STR + e] - m1);
        float rcp = 1.0f / s;

        const int gt = tokBase + t;
        out[(size_t)gt * 2 + 0] = (float)i1;
        out[(size_t)gt * 2 + 1] = (float)i2;
        out[(size_t)2 * S_TOKENS + (size_t)gt * 2 + 0] = rcp;
        out[(size_t)2 * S_TOKENS + (size_t)gt * 2 + 1] = __expf(m2v - m1) * rcp;

        tmax[t] = m1;
        tm2[t]  = m2v;
        trcp[t] = rcp;
        i1s[t]  = i1;
        atomicAdd(&hist[i1], 1);

        if ((m1 - m2v) < DELTA || (m2v - m3v) < DELTA) {
            int idx = atomicAdd(nflag, 1);
            wl[idx] = t;
        }
    }
    __syncthreads();

    // near-tie repair: exact fp32 recompute of candidate experts (warp per token)
    {
        const int nf = nflag[0];
        for (int wi = wid; wi < nf; wi += 8) {
            const int t = wl[wi];
            const float thresh = tm2[t] - DELTA;
            const float4* xr4 = (const float4*)(x + (size_t)(tokBase + t) * D_MODEL);
            float e1 = -1e30f, e2 = -1e30f;
            int j1 = 0, j2 = 0;
            for (int e = 0; e < N_EXP; e++) {
                if (Lp[t * L_STR + e] >= thresh) {   // warp-uniform
                    const float4* wr4 = (const float4*)(wg + (size_t)e * D_MODEL);
                    float s = 0.0f;
#pragma unroll 4
                    for (int i = lane; i < D_MODEL / 4; i += 32) {
                        float4 xv = xr4[i];
                        float4 wv = wr4[i];
                        s += xv.x * wv.x; s += xv.y * wv.y;
                        s += xv.z * wv.z; s += xv.w * wv.w;
                    }
#pragma unroll
                    for (int o = 16; o > 0; o >>= 1)
                        s += __shfl_xor_sync(0xffffffffu, s, o);
                    if (s > e1)      { e2 = e1; j2 = j1; e1 = s; j1 = e; }
                    else if (s > e2) { e2 = s;  j2 = e; }
                }
            }
            if (lane == 0) {
                const int gt = tokBase + t;
                out[(size_t)gt * 2 + 0] = (float)j1;
                out[(size_t)gt * 2 + 1] = (float)j2;
                out[(size_t)2 * S_TOKENS + (size_t)gt * 2 + 0] =
                    __expf(e1 - tmax[t]) * trcp[t];
                out[(size_t)2 * S_TOKENS + (size_t)gt * 2 + 1] =
                    __expf(e2 - tmax[t]) * trcp[t];
                if (j1 != i1s[t]) {
                    atomicAdd(&hist[i1s[t]], -1);
                    atomicAdd(&hist[j1], 1);
                }
            }
        }
    }
    __syncthreads();

    // phase B: per-CTA importance partials + load counts -> global scratch
    {
        const int e = tid & 63;
        const int g = tid >> 6;
        float p = 0.0f;
#pragma unroll
        for (int rr = 0; rr < 32; rr++) {
            int t = g * 32 + rr;
            p += __expf(Lp[t * L_STR + e] - tmax[t]) * trcp[t];
        }
        atomicAdd(&simp[e], p);
    }
    __syncthreads();
    if (tid < N_EXP) {
        part_imp[blk][tid] = simp[tid];
        part_cnt[blk][tid] = hist[tid];
    }

    // ---- last-CTA finalize ----
    __threadfence();
    __syncthreads();
    if (tid == 0) {
        unsigned int old = atomicAdd(&g_ctr, 1u);
        slast[0] = (old == NCTA - 1) ? 1 : 0;
    }
    __syncthreads();
    if (slast[0]) {
        float v = 0.0f;
        if (tid < N_EXP) {
            float vi = 0.0f;
            int   cc = 0;
            for (int cta = 0; cta < NCTA; cta++) {
                vi += part_imp[cta][tid];
                cc += part_cnt[cta][tid];
            }
            v = vi * (float)cc;
        }
#pragma unroll
        for (int o = 16; o > 0; o >>= 1) v += __shfl_down_sync(0xffffffffu, v, o);
        if (tid == 32) simp[1] = v;
        __syncthreads();
        if (tid == 0) {
            float tot = v + simp[1];
            out[(size_t)4 * S_TOKENS] =
                (float)N_EXP * tot / ((float)S_TOKENS * (float)S_TOKENS);
            g_ctr = 0;
        }
    }
}

extern "C" void kernel_launch(void* const* d_in, const int* in_sizes, int n_in,
                              void* d_out, int out_size)
{
    const float* x  = (const float*)d_in[0];
    const float* wg = (const float*)d_in[1];
    float* out = (float*)d_out;

    static int configured = 0;
    if (!configured) {
        cudaFuncSetAttribute(gate_kernel,
                             cudaFuncAttributeMaxDynamicSharedMemorySize, SMEM_B);
        configured = 1;
    }

    prep_kernel<<<N_EXP, 256>>>(wg);
    gate_kernel<<<NCTA, NTHR, SMEM_B>>>(x, wg, out);
}